// round 16
// baseline (speedup 1.0000x reference)
#include <cuda_runtime.h>
#include <cuda_fp16.h>
#include <cstdint>

#define NN   8192
#define FIN  256
#define FOUT 128
#define NC   128        // j-chunks of 64
#define BM   32         // rows per CTA in main kernel
#define GRID_MAIN (NN / BM)   // 256

// ---------------- scratch (static device globals; no allocation) ----------------
__device__ __align__(16) __half g_Wh16[(size_t)NN * FOUT];  // [row j][col c] fp16
__device__ __align__(16) uint2    g_A1[NN / 2];   // per j-pair {f2h2, E2h2}
__device__ __align__(16) unsigned g_A2[NN / 2];   // per j-pair G2h2
__device__ __half g_nf1h[NN];   // (half)(-f1)
__device__ __half g_H1h [NN];   // (half)exp(-0.8 f1)

__device__ __forceinline__ uint32_t sptr(const void* p) {
    return (uint32_t)__cvta_generic_to_shared(p);
}
__device__ __forceinline__ __half2 u2h(uint32_t u) { return *(__half2*)&u; }
__device__ __forceinline__ uint32_t h2u(__half2 h) { return *(uint32_t*)&h; }

// =====================================================================
// Kernel 1: Wh = h @ W (fp32 SIMT GEMM), cp.async double-buffered.
// (R14 configuration, unchanged.)
// =====================================================================
__global__ __launch_bounds__(256, 2) void wh_gemm_kernel(
    const float* __restrict__ h, const float* __restrict__ Wm,
    const float* __restrict__ a)
{
    __shared__ float hs[2][32][36];
    __shared__ float Ws[2][32][132];
    const int tid = threadIdx.x;
    const int i0  = blockIdx.x * 32;
    const int ty  = tid >> 4, tx = tid & 15;

    auto stage = [&](int kt) {
        int k0 = kt * 32, buf = kt & 1;
        {   int r = tid >> 3, c = (tid & 7) * 4;
            asm volatile("cp.async.cg.shared.global [%0],[%1],16;\n"
                :: "r"(sptr(&hs[buf][r][c])),
                   "l"(&h[(size_t)(i0 + r) * FIN + k0 + c]));
        }
        {   int r = tid >> 3, c = (tid & 7) * 16;
#pragma unroll
            for (int q = 0; q < 4; q++)
                asm volatile("cp.async.cg.shared.global [%0],[%1],16;\n"
                    :: "r"(sptr(&Ws[buf][r][c + 4*q])),
                       "l"(&Wm[(size_t)(k0 + r) * FOUT + c + 4*q]));
        }
        asm volatile("cp.async.commit_group;\n");
    };

    float acc[2][8];
#pragma unroll
    for (int u = 0; u < 2; u++)
#pragma unroll
        for (int v = 0; v < 8; v++) acc[u][v] = 0.0f;

    stage(0);
    for (int kt = 0; kt < 8; kt++) {
        asm volatile("cp.async.wait_group 0;\n");
        __syncthreads();
        if (kt < 7) stage(kt + 1);
        const int buf = kt & 1;
#pragma unroll 8
        for (int k = 0; k < 32; k++) {
            float a0 = hs[buf][2*ty][k], a1 = hs[buf][2*ty+1][k];
            float4 b0 = *(const float4*)&Ws[buf][k][8*tx];
            float4 b1 = *(const float4*)&Ws[buf][k][8*tx + 4];
            float bv[8] = {b0.x,b0.y,b0.z,b0.w,b1.x,b1.y,b1.z,b1.w};
#pragma unroll
            for (int v = 0; v < 8; v++) {
                acc[0][v] = fmaf(a0, bv[v], acc[0][v]);
                acc[1][v] = fmaf(a1, bv[v], acc[1][v]);
            }
        }
    }

    float f1a[2] = {0.f, 0.f}, f2a[2] = {0.f, 0.f};
#pragma unroll
    for (int u = 0; u < 2; u++) {
        int row = i0 + 2*ty + u;
#pragma unroll
        for (int q = 0; q < 4; q++) {
            *(__half2*)&g_Wh16[(size_t)row * FOUT + 8*tx + 2*q] =
                __floats2half2_rn(acc[u][2*q], acc[u][2*q+1]);
        }
#pragma unroll
        for (int v = 0; v < 8; v++) {
            int col = 8*tx + v;
            f1a[u] = fmaf(acc[u][v], a[col],        f1a[u]);
            f2a[u] = fmaf(acc[u][v], a[FOUT + col], f2a[u]);
        }
    }
#pragma unroll
    for (int o = 8; o > 0; o >>= 1) {
        f1a[0] += __shfl_xor_sync(0xffffffffu, f1a[0], o);
        f1a[1] += __shfl_xor_sync(0xffffffffu, f1a[1], o);
        f2a[0] += __shfl_xor_sync(0xffffffffu, f2a[0], o);
        f2a[1] += __shfl_xor_sync(0xffffffffu, f2a[1], o);
    }
    if (tx == 0) {
        int k = (i0 >> 1) + ty;         // j-pair index for rows 2ty, 2ty+1
        uint2 a1v;
        a1v.x = h2u(__floats2half2_rn(f2a[0], f2a[1]));
        a1v.y = h2u(__floats2half2_rn(expf(f2a[0]), expf(f2a[1])));
        g_A1[k] = a1v;
        g_A2[k] = h2u(__floats2half2_rn(expf(0.2f*f2a[0]), expf(0.2f*f2a[1])));
#pragma unroll
        for (int u = 0; u < 2; u++) {
            int i = i0 + 2*ty + u;
            g_nf1h[i] = __float2half(-f1a[u]);
            g_H1h[i]  = __float2half(expf(-0.8f * f1a[u]));
        }
    }
}

// =====================================================================
// Kernel 2: fused masked-softmax-attention, fp16 mma.sync.
// R14 base (2m x 8n m16n16 warp tiles — R15's remap reverted) with the
// loop RE-PIPELINED: pgen(ch+2) moved AFTER mma(ch) in the post-barrier
// region, so pgen ALU/LDS overlaps LDSM/HMMA scoreboard stalls within
// each thread. sP writes gain 2 full iterations of slack before their
// consumer (2 barriers), so pgen self-loads its tables (no live-range).
// Commits [A(ch+3)][B(ch+2)], wait_group 3 forces {A(ch+2), B(ch)}.
// adj x3 / sP x3 / sB x4 rings; ONE __syncthreads per chunk.
// =====================================================================
__device__ __forceinline__ void mma_fp16(float* c, const uint32_t* a,
                                         uint32_t b0, uint32_t b1)
{
    asm volatile(
        "mma.sync.aligned.m16n8k16.row.col.f32.f16.f16.f32 "
        "{%0,%1,%2,%3},{%4,%5,%6,%7},{%8,%9},{%0,%1,%2,%3};\n"
        : "+f"(c[0]), "+f"(c[1]), "+f"(c[2]), "+f"(c[3])
        : "r"(a[0]), "r"(a[1]), "r"(a[2]), "r"(a[3]), "r"(b0), "r"(b1));
}

#define ADJ_SLOT 8192u       // 32 x 64 ints
#define SP_SLOT  4608u       // 32 x 72 halfs (144B rows)
#define SB_SLOT  17408u      // 64 x 136 halfs (272B rows)
#define DYN_SMEM (3*ADJ_SLOT + 3*SP_SLOT + 4*SB_SLOT)   // 108032

__global__ __launch_bounds__(512, 2) void gat_main_kernel(
    const int* __restrict__ adj, float* __restrict__ out)
{
    extern __shared__ char dynsm[];
    __shared__ float sden[BM];

    const int tid  = threadIdx.x;
    const int lane = tid & 31;
    const int warp = tid >> 5;     // 0..15
    const int r    = tid >> 4;     // 0..31  (pgen/adj row)
    const int cq   = tid & 15;     // col group of 4
    const int i0   = blockIdx.x * BM;
    const int wm   = warp & 1;     // m16 position (2)
    const int wn   = warp >> 1;    // n16 position (8)

    const uint32_t adjS = sptr(dynsm);
    const uint32_t spS  = adjS + 3 * ADJ_SLOT;
    const uint32_t sbS  = spS  + 3 * SP_SLOT;

    const __half2 nf1r2 = __half2half2(g_nf1h[i0 + r]);
    const __half2 H1r2  = __half2half2(g_H1h [i0 + r]);
    float den = 0.0f;

    float acc[2][4];
#pragma unroll
    for (int nf = 0; nf < 2; nf++)
#pragma unroll
        for (int q = 0; q < 4; q++) acc[nf][q] = 0.0f;

    // ---- stage helpers (each always commits exactly one group) ----
    auto stage_adj = [&](int ch) {
        if (ch < NC) {
            const int* src = &adj[(size_t)(i0 + r) * NN + ch * 64 + 4 * cq];
            uint32_t dst = adjS + (uint32_t)(ch % 3) * ADJ_SLOT
                         + (uint32_t)(r * 256 + 16 * cq);
            asm volatile("cp.async.cg.shared.global [%0],[%1],16;\n" :: "r"(dst), "l"(src));
        }
        asm volatile("cp.async.commit_group;\n");
    };
    auto stage_B = [&](int ch) {
        if (ch < NC) {
            const int j0 = ch * 64;
            uint32_t base = sbS + (uint32_t)(ch & 3) * SB_SLOT;
#pragma unroll
            for (int i = 0; i < 2; i++) {
                int seg = tid + 512 * i;          // 0..1023
                int rr = seg >> 4, ss = seg & 15;
                const __half* src = &g_Wh16[(size_t)(j0 + rr) * FOUT + 8 * ss];
                uint32_t dst = base + (uint32_t)(rr * 272 + 16 * ss);
                asm volatile("cp.async.cg.shared.global [%0],[%1],16;\n" :: "r"(dst), "l"(src));
            }
        }
        asm volatile("cp.async.commit_group;\n");
    };

    // pgen: packed half2 tables (self-loaded — 2 iterations of slack),
    // mask-select; fp32 den from the SAME fp16 weights the MMA consumes.
    auto pgen = [&](int ch) {
        uint4 t1 = __ldg((const uint4*)&g_A1[ch * 32 + 2 * cq]);
        uint2 t2 = __ldg((const uint2*)&g_A2[ch * 32 + 2 * cq]);
        uint32_t aoff = adjS + (uint32_t)(ch % 3) * ADJ_SLOT
                      + (uint32_t)(r * 256 + 16 * cq);
        int4 a0;
        asm volatile("ld.shared.v4.b32 {%0,%1,%2,%3},[%4];"
                     : "=r"(a0.x), "=r"(a0.y), "=r"(a0.z), "=r"(a0.w) : "r"(aoff));
        uint32_t gA = __hgt2_mask(u2h(t1.x), nf1r2);
        uint32_t gB = __hgt2_mask(u2h(t1.z), nf1r2);
        uint32_t tA = h2u(__hmul2(H1r2, u2h(t2.x)));
        uint32_t tB = h2u(__hmul2(H1r2, u2h(t2.y)));
        uint32_t selA = (t1.y & gA) | (tA & ~gA);
        uint32_t selB = (t1.w & gB) | (tB & ~gB);
        uint32_t mA = (a0.x > 0 ? 0xFFFFu : 0u) | (a0.y > 0 ? 0xFFFF0000u : 0u);
        uint32_t mB = (a0.z > 0 ? 0xFFFFu : 0u) | (a0.w > 0 ? 0xFFFF0000u : 0u);
        uint32_t wA = selA & mA, wB = selB & mB;
        float2 fa = __half22float2(u2h(wA));
        float2 fb = __half22float2(u2h(wB));
        den += fa.x + fa.y + fb.x + fb.y;
        uint32_t dst = spS + (uint32_t)(ch % 3) * SP_SLOT
                     + (uint32_t)(r * 144 + 8 * cq);
        asm volatile("st.shared.v2.b32 [%0],{%1,%2};"
                     :: "r"(dst), "r"(wA), "r"(wB) : "memory");
    };

    auto mma_phase = [&](int ch) {
        uint32_t sp = spS + (uint32_t)(ch % 3) * SP_SLOT;
        uint32_t sb = sbS + (uint32_t)(ch & 3) * SB_SLOT;
        const int mi = lane >> 3, l7 = lane & 7;
        uint32_t spA = sp + (uint32_t)((16*wm + ((mi & 1) << 3) + l7) * 144
                                       + (((mi >> 1) << 3)) * 2);
        uint32_t sbB = sb + (uint32_t)((((mi & 1) << 3) + l7) * 272
                                       + (16*wn + ((mi >> 1) << 3)) * 2);
#pragma unroll
        for (int kk = 0; kk < 4; kk++) {
            uint32_t afr[4];
            asm volatile(
                "ldmatrix.sync.aligned.m8n8.x4.shared.b16 {%0,%1,%2,%3},[%4];\n"
                : "=r"(afr[0]), "=r"(afr[1]), "=r"(afr[2]), "=r"(afr[3])
                : "r"(spA + (uint32_t)(32 * kk)));
            uint32_t b[4];
            asm volatile(
                "ldmatrix.sync.aligned.m8n8.x4.trans.shared.b16 {%0,%1,%2,%3},[%4];\n"
                : "=r"(b[0]), "=r"(b[1]), "=r"(b[2]), "=r"(b[3])
                : "r"(sbB + (uint32_t)(16 * kk * 272)));
            mma_fp16(acc[0], afr, b[0], b[1]);
            mma_fp16(acc[1], afr, b[2], b[3]);
        }
    };

    // ---- prologue: commits [A0][A1][B0][A2][B1]; wait forces A0, A1 ----
    stage_adj(0);
    stage_adj(1);
    stage_B(0);
    stage_adj(2);
    stage_B(1);
    asm volatile("cp.async.wait_group 3;\n");   // forces A1, A0
    pgen(0);
    pgen(1);

    // ---- main loop: commits [A(ch+3)][B(ch+2)]; wait_group 3 forces
    //      {A(ch+2), B(ch)}; post-barrier region = mma(ch) + pgen(ch+2)
    //      (independent -> ILP overlap). ONE barrier per chunk.
    for (int ch = 0; ch < NC; ch++) {
        stage_adj(ch + 3);
        stage_B(ch + 2);
        asm volatile("cp.async.wait_group 3;\n");
        __syncthreads();                // publishes P(ch) (written 2 iters ago)
        mma_phase(ch);
        if (ch + 2 < NC) pgen(ch + 2);
    }

    // ---- denominator reduction (16 threads per row) ----
    den += __shfl_xor_sync(0xffffffffu, den, 1);
    den += __shfl_xor_sync(0xffffffffu, den, 2);
    den += __shfl_xor_sync(0xffffffffu, den, 4);
    den += __shfl_xor_sync(0xffffffffu, den, 8);
    if (cq == 0) sden[r] = den;
    __syncthreads();

    // ---- epilogue: normalize, write fp32 output ----
    const int g = lane >> 2, t = lane & 3;
    {
        int row0 = 16*wm + g;
        float inv0 = 1.0f / sden[row0];
        float inv1 = 1.0f / sden[row0 + 8];
#pragma unroll
        for (int nf = 0; nf < 2; nf++) {
            int col = 16*wn + 8*nf + 2*t;
            out[(size_t)(i0 + row0)     * FOUT + col    ] = acc[nf][0] * inv0;
            out[(size_t)(i0 + row0)     * FOUT + col + 1] = acc[nf][1] * inv0;
            out[(size_t)(i0 + row0 + 8) * FOUT + col    ] = acc[nf][2] * inv1;
            out[(size_t)(i0 + row0 + 8) * FOUT + col + 1] = acc[nf][3] * inv1;
        }
    }
}

// =====================================================================
extern "C" void kernel_launch(void* const* d_in, const int* in_sizes, int n_in,
                              void* d_out, int out_size)
{
    const float* h   = (const float*)d_in[0];   // [8192,256] f32
    const int*   adj = (const int*)  d_in[1];   // [8192,8192] i32
    const float* Wm  = (const float*)d_in[2];   // [256,128] f32
    const float* a   = (const float*)d_in[3];   // [256,1] f32
    float* out = (float*)d_out;                 // [8192,128] f32

    cudaFuncSetAttribute(gat_main_kernel,
                         cudaFuncAttributeMaxDynamicSharedMemorySize, DYN_SMEM);

    wh_gemm_kernel <<<256, 256>>>(h, Wm, a);
    gat_main_kernel<<<GRID_MAIN, 512, DYN_SMEM>>>(adj, out);
}

// round 17
// speedup vs baseline: 1.2190x; 1.2190x over previous
#include <cuda_runtime.h>
#include <cuda_fp16.h>
#include <cstdint>

#define NN   8192
#define FIN  256
#define FOUT 128
#define NC   128        // j-chunks of 64
#define BM   32         // rows per CTA in main kernel
#define GRID_MAIN (NN / BM)   // 256

// ---------------- scratch (static device globals; no allocation) ----------------
__device__ __align__(16) __half g_h16 [(size_t)NN * FIN];   // fp16 copy of h
__device__ __align__(16) __half g_W16 [(size_t)FIN * FOUT]; // fp16 copy of W
__device__ __align__(16) __half g_Wh16[(size_t)NN * FOUT];  // [row j][col c] fp16
__device__ __align__(16) uint2    g_A1[NN / 2];   // per j-pair {f2h2, E2h2}
__device__ __align__(16) unsigned g_A2[NN / 2];   // per j-pair G2h2
__device__ __half g_nf1h[NN];   // (half)(-f1)
__device__ __half g_H1h [NN];   // (half)exp(-0.8 f1)

__device__ __forceinline__ uint32_t sptr(const void* p) {
    return (uint32_t)__cvta_generic_to_shared(p);
}
__device__ __forceinline__ __half2 u2h(uint32_t u) { return *(__half2*)&u; }
__device__ __forceinline__ uint32_t h2u(__half2 h) { return *(uint32_t*)&h; }

__device__ __forceinline__ void mma_fp16(float* c, const uint32_t* a,
                                         uint32_t b0, uint32_t b1)
{
    asm volatile(
        "mma.sync.aligned.m16n8k16.row.col.f32.f16.f16.f32 "
        "{%0,%1,%2,%3},{%4,%5,%6,%7},{%8,%9},{%0,%1,%2,%3};\n"
        : "+f"(c[0]), "+f"(c[1]), "+f"(c[2]), "+f"(c[3])
        : "r"(a[0]), "r"(a[1]), "r"(a[2]), "r"(a[3]), "r"(b0), "r"(b1));
}

// =====================================================================
// Kernel 0: convert h and W to fp16. grid 1040 x 256 (8 elems/thread).
// blocks 0..1023: h (2M elems); blocks 1024..1039: W (32K elems).
// =====================================================================
__global__ __launch_bounds__(256) void cvt_kernel(
    const float* __restrict__ h, const float* __restrict__ Wm)
{
    const int b = blockIdx.x;
    const float* src;
    __half* dst;
    size_t base;
    if (b < 1024) { src = h;  dst = g_h16; base = (size_t)b * 2048; }
    else          { src = Wm; dst = g_W16; base = (size_t)(b - 1024) * 2048; }
    size_t off = base + (size_t)threadIdx.x * 8;
    float4 v0 = *(const float4*)&src[off];
    float4 v1 = *(const float4*)&src[off + 4];
    __half2 o0 = __floats2half2_rn(v0.x, v0.y);
    __half2 o1 = __floats2half2_rn(v0.z, v0.w);
    __half2 o2 = __floats2half2_rn(v1.x, v1.y);
    __half2 o3 = __floats2half2_rn(v1.z, v1.w);
    uint2 p0 = make_uint2(h2u(o0), h2u(o1));
    uint2 p1 = make_uint2(h2u(o2), h2u(o3));
    *(uint2*)&dst[off]     = p0;
    *(uint2*)&dst[off + 4] = p1;
}

// =====================================================================
// Kernel 1: Wh = h16 @ W16 via mma.sync (fp16 in, fp32 accum).
// grid 64, 256 thr; tile M128 x N128, K=256 in 8 chunks of 32
// (cp.async double-buffered). Warp grid 4m x 2n, warp tile m32n64.
// Epilogue: fp16 Wh + f1/f2 row dots + exp tables (fused).
// =====================================================================
__global__ __launch_bounds__(256) void wh_mma_kernel(const float* __restrict__ a)
{
    __shared__ __half sH[2][128][40];    // h chunk, 80B rows
    __shared__ __half sW[2][32][136];    // W chunk, 272B rows
    __shared__ float  sA[2 * FOUT];      // a1[128], a2[128]
    __shared__ float  sF[2][128][2];     // [wn][row][f1,f2] partials

    const int tid  = threadIdx.x;
    const int lane = tid & 31;
    const int warp = tid >> 5;
    const int wm   = warp & 3;     // m32 tile (4)
    const int wn   = warp >> 2;    // n64 tile (2)
    const int i0   = blockIdx.x * 128;

    sA[tid] = a[tid];              // 256 floats

    auto stage = [&](int kt) {
        const int buf = kt & 1;
#pragma unroll
        for (int i = 0; i < 2; i++) {   // h chunk: 512 16B segs
            int seg = tid + 256 * i;
            int row = seg >> 2, s = seg & 3;
            asm volatile("cp.async.cg.shared.global [%0],[%1],16;\n"
                :: "r"(sptr(&sH[buf][row][8 * s])),
                   "l"(&g_h16[(size_t)(i0 + row) * FIN + kt * 32 + 8 * s]));
        }
#pragma unroll
        for (int i = 0; i < 2; i++) {   // W chunk: 512 16B segs
            int seg = tid + 256 * i;
            int row = seg >> 4, s = seg & 15;
            asm volatile("cp.async.cg.shared.global [%0],[%1],16;\n"
                :: "r"(sptr(&sW[buf][row][8 * s])),
                   "l"(&g_W16[(size_t)(kt * 32 + row) * FOUT + 8 * s]));
        }
        asm volatile("cp.async.commit_group;\n");
    };

    float acc[2][8][4];
#pragma unroll
    for (int mf = 0; mf < 2; mf++)
#pragma unroll
        for (int nf = 0; nf < 8; nf++)
#pragma unroll
            for (int q = 0; q < 4; q++) acc[mf][nf][q] = 0.0f;

    stage(0);
    const int mi = lane >> 3, l7 = lane & 7;
    for (int kt = 0; kt < 8; kt++) {
        asm volatile("cp.async.wait_group 0;\n");
        __syncthreads();
        if (kt < 7) stage(kt + 1);
        const int buf = kt & 1;
#pragma unroll
        for (int ks = 0; ks < 2; ks++) {
            uint32_t afr[2][4];
#pragma unroll
            for (int mf = 0; mf < 2; mf++) {
                uint32_t addr = sptr(&sH[buf][32*wm + 16*mf + ((mi & 1) << 3) + l7]
                                        [16*ks + ((mi >> 1) << 3)]);
                asm volatile(
                    "ldmatrix.sync.aligned.m8n8.x4.shared.b16 {%0,%1,%2,%3},[%4];\n"
                    : "=r"(afr[mf][0]), "=r"(afr[mf][1]),
                      "=r"(afr[mf][2]), "=r"(afr[mf][3])
                    : "r"(addr));
            }
#pragma unroll
            for (int nf = 0; nf < 4; nf++) {
                uint32_t b[4];
                uint32_t addr = sptr(&sW[buf][16*ks + ((mi & 1) << 3) + l7]
                                        [64*wn + 16*nf + ((mi >> 1) << 3)]);
                asm volatile(
                    "ldmatrix.sync.aligned.m8n8.x4.trans.shared.b16 {%0,%1,%2,%3},[%4];\n"
                    : "=r"(b[0]), "=r"(b[1]), "=r"(b[2]), "=r"(b[3])
                    : "r"(addr));
#pragma unroll
                for (int mf = 0; mf < 2; mf++) {
                    mma_fp16(acc[mf][2*nf],     afr[mf], b[0], b[1]);
                    mma_fp16(acc[mf][2*nf + 1], afr[mf], b[2], b[3]);
                }
            }
        }
    }

    // ---- epilogue: fp16 Wh store + f1/f2 partial dots ----
    const int g = lane >> 2, t = lane & 3;
    float f1p[2][2] = {{0.f,0.f},{0.f,0.f}};
    float f2p[2][2] = {{0.f,0.f},{0.f,0.f}};
#pragma unroll
    for (int mf = 0; mf < 2; mf++) {
        int lr0 = 32*wm + 16*mf + g;
#pragma unroll
        for (int nf = 0; nf < 8; nf++) {
            int c = 64*wn + 8*nf + 2*t;
            *(__half2*)&g_Wh16[(size_t)(i0 + lr0) * FOUT + c] =
                __floats2half2_rn(acc[mf][nf][0], acc[mf][nf][1]);
            *(__half2*)&g_Wh16[(size_t)(i0 + lr0 + 8) * FOUT + c] =
                __floats2half2_rn(acc[mf][nf][2], acc[mf][nf][3]);
            float a1c = sA[c], a1d = sA[c + 1];
            float a2c = sA[FOUT + c], a2d = sA[FOUT + c + 1];
            f1p[mf][0] += acc[mf][nf][0]*a1c + acc[mf][nf][1]*a1d;
            f1p[mf][1] += acc[mf][nf][2]*a1c + acc[mf][nf][3]*a1d;
            f2p[mf][0] += acc[mf][nf][0]*a2c + acc[mf][nf][1]*a2d;
            f2p[mf][1] += acc[mf][nf][2]*a2c + acc[mf][nf][3]*a2d;
        }
    }
#pragma unroll
    for (int o = 1; o <= 2; o <<= 1) {
#pragma unroll
        for (int mf = 0; mf < 2; mf++)
#pragma unroll
            for (int u = 0; u < 2; u++) {
                f1p[mf][u] += __shfl_xor_sync(0xffffffffu, f1p[mf][u], o);
                f2p[mf][u] += __shfl_xor_sync(0xffffffffu, f2p[mf][u], o);
            }
    }
    if (t == 0) {
#pragma unroll
        for (int mf = 0; mf < 2; mf++) {
            int lr0 = 32*wm + 16*mf + g;
            sF[wn][lr0][0]     = f1p[mf][0];
            sF[wn][lr0][1]     = f2p[mf][0];
            sF[wn][lr0 + 8][0] = f1p[mf][1];
            sF[wn][lr0 + 8][1] = f2p[mf][1];
        }
    }
    __syncthreads();

    // ---- finalize: exp tables per row pair (64 threads) ----
    if (tid < 64) {
        int q = tid;
        float f1a = sF[0][2*q][0]     + sF[1][2*q][0];
        float f1b = sF[0][2*q + 1][0] + sF[1][2*q + 1][0];
        float f2a = sF[0][2*q][1]     + sF[1][2*q][1];
        float f2b = sF[0][2*q + 1][1] + sF[1][2*q + 1][1];
        int row0 = i0 + 2*q;
        int k = row0 >> 1;
        uint2 a1v;
        a1v.x = h2u(__floats2half2_rn(f2a, f2b));
        a1v.y = h2u(__floats2half2_rn(expf(f2a), expf(f2b)));
        g_A1[k] = a1v;
        g_A2[k] = h2u(__floats2half2_rn(expf(0.2f*f2a), expf(0.2f*f2b)));
        g_nf1h[row0]     = __float2half(-f1a);
        g_nf1h[row0 + 1] = __float2half(-f1b);
        g_H1h[row0]      = __float2half(expf(-0.8f * f1a));
        g_H1h[row0 + 1]  = __float2half(expf(-0.8f * f1b));
    }
}

// =====================================================================
// Kernel 2: fused masked-softmax-attention, fp16 mma.sync.
// (R14 main kernel, byte-identical — best measured configuration.)
// =====================================================================
#define ADJ_SLOT 8192u       // 32 x 64 ints
#define SP_SLOT  4608u       // 32 x 72 halfs (144B rows)
#define SB_SLOT  17408u      // 64 x 136 halfs (272B rows)
#define DYN_SMEM (3*ADJ_SLOT + 3*SP_SLOT + 4*SB_SLOT)   // 108032

__global__ __launch_bounds__(512, 2) void gat_main_kernel(
    const int* __restrict__ adj, float* __restrict__ out)
{
    extern __shared__ char dynsm[];
    __shared__ float sden[BM];

    const int tid  = threadIdx.x;
    const int lane = tid & 31;
    const int warp = tid >> 5;     // 0..15
    const int r    = tid >> 4;     // 0..31  (pgen/adj row)
    const int cq   = tid & 15;     // col group of 4
    const int i0   = blockIdx.x * BM;
    const int wm   = warp & 1;     // m16 position (2)
    const int wn   = warp >> 1;    // n16 position (8)

    const uint32_t adjS = sptr(dynsm);
    const uint32_t spS  = adjS + 3 * ADJ_SLOT;
    const uint32_t sbS  = spS  + 3 * SP_SLOT;

    const __half2 nf1r2 = __half2half2(g_nf1h[i0 + r]);
    const __half2 H1r2  = __half2half2(g_H1h [i0 + r]);
    float den = 0.0f;

    float acc[2][4];
#pragma unroll
    for (int nf = 0; nf < 2; nf++)
#pragma unroll
        for (int q = 0; q < 4; q++) acc[nf][q] = 0.0f;

    // ---- stage helpers (each always commits exactly one group) ----
    auto stage_adj = [&](int ch) {
        if (ch < NC) {
            const int* src = &adj[(size_t)(i0 + r) * NN + ch * 64 + 4 * cq];
            uint32_t dst = adjS + (uint32_t)(ch % 3) * ADJ_SLOT
                         + (uint32_t)(r * 256 + 16 * cq);
            asm volatile("cp.async.cg.shared.global [%0],[%1],16;\n" :: "r"(dst), "l"(src));
        }
        asm volatile("cp.async.commit_group;\n");
    };
    auto stage_B = [&](int ch) {
        if (ch < NC) {
            const int j0 = ch * 64;
            uint32_t base = sbS + (uint32_t)(ch & 3) * SB_SLOT;
#pragma unroll
            for (int i = 0; i < 2; i++) {
                int seg = tid + 512 * i;          // 0..1023
                int rr = seg >> 4, ss = seg & 15;
                const __half* src = &g_Wh16[(size_t)(j0 + rr) * FOUT + 8 * ss];
                uint32_t dst = base + (uint32_t)(rr * 272 + 16 * ss);
                asm volatile("cp.async.cg.shared.global [%0],[%1],16;\n" :: "r"(dst), "l"(src));
            }
        }
        asm volatile("cp.async.commit_group;\n");
    };

    // pgen: packed half2 tables, mask-select; fp32 den from the SAME
    // fp16 weights the MMA consumes.
    auto pgen_rest = [&](int ch, uint4 t1, uint2 t2) {
        uint32_t aoff = adjS + (uint32_t)(ch % 3) * ADJ_SLOT
                      + (uint32_t)(r * 256 + 16 * cq);
        int4 a0;
        asm volatile("ld.shared.v4.b32 {%0,%1,%2,%3},[%4];"
                     : "=r"(a0.x), "=r"(a0.y), "=r"(a0.z), "=r"(a0.w) : "r"(aoff));
        uint32_t gA = __hgt2_mask(u2h(t1.x), nf1r2);
        uint32_t gB = __hgt2_mask(u2h(t1.z), nf1r2);
        uint32_t tA = h2u(__hmul2(H1r2, u2h(t2.x)));
        uint32_t tB = h2u(__hmul2(H1r2, u2h(t2.y)));
        uint32_t selA = (t1.y & gA) | (tA & ~gA);
        uint32_t selB = (t1.w & gB) | (tB & ~gB);
        uint32_t mA = (a0.x > 0 ? 0xFFFFu : 0u) | (a0.y > 0 ? 0xFFFF0000u : 0u);
        uint32_t mB = (a0.z > 0 ? 0xFFFFu : 0u) | (a0.w > 0 ? 0xFFFF0000u : 0u);
        uint32_t wA = selA & mA, wB = selB & mB;
        float2 fa = __half22float2(u2h(wA));
        float2 fb = __half22float2(u2h(wB));
        den += fa.x + fa.y + fb.x + fb.y;
        uint32_t dst = spS + (uint32_t)(ch % 3) * SP_SLOT
                     + (uint32_t)(r * 144 + 8 * cq);
        asm volatile("st.shared.v2.b32 [%0],{%1,%2};"
                     :: "r"(dst), "r"(wA), "r"(wB) : "memory");
    };

    auto mma_phase = [&](int ch) {
        uint32_t sp = spS + (uint32_t)(ch % 3) * SP_SLOT;
        uint32_t sb = sbS + (uint32_t)(ch & 3) * SB_SLOT;
        const int mi = lane >> 3, l7 = lane & 7;
        uint32_t spA = sp + (uint32_t)((16*wm + ((mi & 1) << 3) + l7) * 144
                                       + (((mi >> 1) << 3)) * 2);
        uint32_t sbB = sb + (uint32_t)((((mi & 1) << 3) + l7) * 272
                                       + (16*wn + ((mi >> 1) << 3)) * 2);
#pragma unroll
        for (int kk = 0; kk < 4; kk++) {
            uint32_t afr[4];
            asm volatile(
                "ldmatrix.sync.aligned.m8n8.x4.shared.b16 {%0,%1,%2,%3},[%4];\n"
                : "=r"(afr[0]), "=r"(afr[1]), "=r"(afr[2]), "=r"(afr[3])
                : "r"(spA + (uint32_t)(32 * kk)));
            uint32_t b[4];
            asm volatile(
                "ldmatrix.sync.aligned.m8n8.x4.trans.shared.b16 {%0,%1,%2,%3},[%4];\n"
                : "=r"(b[0]), "=r"(b[1]), "=r"(b[2]), "=r"(b[3])
                : "r"(sbB + (uint32_t)(16 * kk * 272)));
            mma_fp16(acc[0], afr, b[0], b[1]);
            mma_fp16(acc[1], afr, b[2], b[3]);
        }
    };

    // ---- prologue: commits [A0][B0][A1][B1][A2] ----
    stage_adj(0);
    stage_B(0);
    stage_adj(1);
    stage_B(1);
    stage_adj(2);
    {
        uint4 t1 = __ldg((const uint4*)&g_A1[2 * cq]);
        uint2 t2 = __ldg((const uint2*)&g_A2[2 * cq]);
        asm volatile("cp.async.wait_group 4;\n");   // forces A0
        pgen_rest(0, t1, t2);
    }

    // ---- main loop: commits per iter [B(ch+2)][A(ch+3)], 1 barrier ----
    for (int ch = 0; ch < NC; ch++) {
        stage_B(ch + 2);
        stage_adj(ch + 3);
        const int chn = ch + 1;
        uint4 t1; uint2 t2;
        if (chn < NC) {                 // hoisted: no cp.async dependency
            t1 = __ldg((const uint4*)&g_A1[chn * 32 + 2 * cq]);
            t2 = __ldg((const uint2*)&g_A2[chn * 32 + 2 * cq]);
        }
        asm volatile("cp.async.wait_group 4;\n");   // forces B(ch), A(ch+1)
        if (chn < NC) pgen_rest(chn, t1, t2);
        __syncthreads();                // publishes P(ch)/B(ch); guards reuse
        mma_phase(ch);
    }

    // ---- denominator reduction (16 threads per row) ----
    den += __shfl_xor_sync(0xffffffffu, den, 1);
    den += __shfl_xor_sync(0xffffffffu, den, 2);
    den += __shfl_xor_sync(0xffffffffu, den, 4);
    den += __shfl_xor_sync(0xffffffffu, den, 8);
    if (cq == 0) sden[r] = den;
    __syncthreads();

    // ---- epilogue: normalize, write fp32 output ----
    const int g = lane >> 2, t = lane & 3;
    {
        int row0 = 16*wm + g;
        float inv0 = 1.0f / sden[row0];
        float inv1 = 1.0f / sden[row0 + 8];
#pragma unroll
        for (int nf = 0; nf < 2; nf++) {
            int col = 16*wn + 8*nf + 2*t;
            out[(size_t)(i0 + row0)     * FOUT + col    ] = acc[nf][0] * inv0;
            out[(size_t)(i0 + row0)     * FOUT + col + 1] = acc[nf][1] * inv0;
            out[(size_t)(i0 + row0 + 8) * FOUT + col    ] = acc[nf][2] * inv1;
            out[(size_t)(i0 + row0 + 8) * FOUT + col + 1] = acc[nf][3] * inv1;
        }
    }
}

// =====================================================================
extern "C" void kernel_launch(void* const* d_in, const int* in_sizes, int n_in,
                              void* d_out, int out_size)
{
    const float* h   = (const float*)d_in[0];   // [8192,256] f32
    const int*   adj = (const int*)  d_in[1];   // [8192,8192] i32
    const float* Wm  = (const float*)d_in[2];   // [256,128] f32
    const float* a   = (const float*)d_in[3];   // [256,1] f32
    float* out = (float*)d_out;                 // [8192,128] f32

    cudaFuncSetAttribute(gat_main_kernel,
                         cudaFuncAttributeMaxDynamicSharedMemorySize, DYN_SMEM);

    cvt_kernel     <<<1040, 256>>>(h, Wm);
    wh_mma_kernel  <<<64, 256>>>(a);
    gat_main_kernel<<<GRID_MAIN, 512, DYN_SMEM>>>(adj, out);
}